// round 8
// baseline (speedup 1.0000x reference)
#include <cuda_runtime.h>
#include <cstdint>
#include <math.h>

// Problem constants
constexpr int B_  = 8;
constexpr int C_  = 256;
constexpr int H_  = 31;
constexpr int W_  = 31;
constexpr int T_  = 7;
constexpr int K_  = 49;      // T*T
constexpr int OC_ = 147;     // 3*K
constexpr int NP_ = 74;      // oc pairs (padded 148)
constexpr int OH_ = 25;
constexpr int OW_ = 25;
constexpr int HW_ = H_ * W_; // 961
constexpr int OHW_= OH_ * OW_; // 625
constexpr int CT_ = 8;       // C split tiles
constexpr int CPT_= C_ / CT_;// 32 channels per tile
constexpr int YT_ = 9;       // y tiles of 3 rows

// Scratch (device globals; no allocations allowed)
__device__ float g_srT[B_ * HW_ * C_];                 // (B,H,W,C)
__device__ float g_tmplT[B_ * K_ * C_];                // (B,K,C)
__device__ float g_om[B_ * OC_ * OHW_];                // reduced conv out
__device__ float g_part[CT_ * B_ * OC_ * OHW_];        // conv partials
__device__ float2 g_wpk[C_ * NP_ * 9];                 // packed weights [c][pair][tap]

// packed f32x2 helpers
#define FMA_F32X2(d, a, b, c) \
    asm("fma.rn.f32x2 %0, %1, %2, %3;" : "=l"(d) : "l"(a), "l"(b), "l"(c))
#define UNPACK2(lo, hi, p) \
    asm("mov.b64 {%0, %1}, %2;" : "=f"(lo), "=f"(hi) : "l"(p))

// ---------------------------------------------------------------------------
// Fused prep: transpose sr, transpose tmpl, pack weights — one launch.
// grid.x partition: [0,1984) sr-transpose, [1984,2376) tmpl, [2376,3042) pack.
// ---------------------------------------------------------------------------
constexpr int PREP_SR_BLKS   = 31 * 8 * 8;             // 1984
constexpr int PREP_TMPL_BLKS = (B_ * K_ * C_ + 255) / 256;   // 392
constexpr int PREP_PACK_BLKS = (C_ * NP_ * 9 + 255) / 256;   // 666
constexpr int PREP_BLKS = PREP_SR_BLKS + PREP_TMPL_BLKS + PREP_PACK_BLKS;

__global__ void __launch_bounds__(256) prep_kernel(
    const float* __restrict__ sr,
    const float* __restrict__ tmpl,
    const float* __restrict__ w)
{
    __shared__ float tile[32][33];
    const int bid = blockIdx.x;
    const int tid = threadIdx.x;

    if (bid < PREP_SR_BLKS) {
        // transpose sr (B,C,HW) -> (B,HW,C); virtual grid (31, 8, 8)
        int px = bid % 31;
        int cy = (bid / 31) % 8;
        int b  = bid / (31 * 8);
        int p0 = px * 32, c0 = cy * 32;
        int tx = tid % 32, ty = tid / 32;
        #pragma unroll
        for (int yy = 0; yy < 32; yy += 8) {
            int c = c0 + ty + yy, p = p0 + tx;
            if (p < HW_) tile[ty + yy][tx] = sr[(b * C_ + c) * HW_ + p];
        }
        __syncthreads();
        #pragma unroll
        for (int yy = 0; yy < 32; yy += 8) {
            int p = p0 + ty + yy, c = c0 + tx;
            if (p < HW_) g_srT[(b * HW_ + p) * C_ + c] = tile[tx][ty + yy];
        }
    } else if (bid < PREP_SR_BLKS + PREP_TMPL_BLKS) {
        int t = (bid - PREP_SR_BLKS) * 256 + tid;
        if (t < B_ * K_ * C_) {
            int c = t % C_;
            int k = (t / C_) % K_;
            int b = t / (C_ * K_);
            g_tmplT[t] = tmpl[(b * C_ + c) * K_ + k];
        }
    } else {
        int t = (bid - PREP_SR_BLKS - PREP_TMPL_BLKS) * 256 + tid;
        if (t < C_ * NP_ * 9) {
            int tap = t % 9;
            int p   = (t / 9) % NP_;
            int c   = t / (9 * NP_);
            int o0 = 2 * p, o1 = 2 * p + 1;
            float v0 = w[o0 * (C_ * 9) + c * 9 + tap];
            float v1 = (o1 < OC_) ? w[o1 * (C_ * 9) + c * 9 + tap] : 0.0f;
            g_wpk[t] = make_float2(v0, v1);
        }
    }
}

// ---------------------------------------------------------------------------
// K2: 3x3 conv on cropped region, f32x2 packed math, split-C partials.
// grid = (YT_=9, B_=8, CT_=8) = 576 blocks (1.95 waves @ 2 blocks/SM).
// block = 384; og=tid/5 (74 oc-pairs), xg=tid%5 (5 x each), 3 output rows.
// sr slice staged into smem ONCE as DUPLICATED float2 (v,v): inner loop is
// LDS.64 -> FFMA2 directly, no per-value mov.b64 duplication.
// Weights read per-thread via LDG (L1/L2-cached) — no smem.
// ---------------------------------------------------------------------------
__global__ void __launch_bounds__(384, 2) conv_om_kernel(
    const float* __restrict__ sr)
{
    __shared__ float2 s_sr[CPT_][5][33];   // 42.2 KB

    const int by = blockIdx.x;
    const int b  = blockIdx.y;
    const int ct = blockIdx.z;
    const int tid = threadIdx.x;

    const int og = tid / 5;          // 0..76
    const int xg = tid % 5;
    const bool active = (og < NP_);  // 370 active
    const int x_base = xg * 5;
    const int y_base = by * 3;
    const int cbase  = ct * CPT_;

    // stage sr slice: 32 ch x rows y_base-1..y_base+3 x padded cols -1..31
    for (int e = tid; e < CPT_ * 5 * 33; e += 384) {
        int cc  = e / 165;
        int rem = e % 165;
        int r   = rem / 33;
        int xp  = rem % 33;
        int gy  = y_base + r - 1;
        int gx  = xp - 1;
        float v = 0.f;
        if (gy >= 0 && gy < H_ && gx >= 0 && gx < W_)
            v = sr[((b * C_ + cbase + cc) * H_ + gy) * W_ + gx];
        s_sr[cc][r][xp] = make_float2(v, v);
    }
    __syncthreads();

    unsigned long long acc[3][5];    // [yy][xx]
    #pragma unroll
    for (int yy = 0; yy < 3; yy++)
        #pragma unroll
        for (int xx = 0; xx < 5; xx++) acc[yy][xx] = 0ull;

    if (active) {
        const unsigned long long* __restrict__ wp0 =
            (const unsigned long long*)g_wpk + (size_t)og * 9;
        #pragma unroll 2
        for (int c = 0; c < CPT_; c++) {
            unsigned long long wq[9];
            const unsigned long long* wp = wp0 + (size_t)(cbase + c) * (NP_ * 9);
            #pragma unroll
            for (int t = 0; t < 9; t++) wq[t] = __ldg(wp + t);

            #pragma unroll
            for (int ir = 0; ir < 5; ir++) {
                #pragma unroll
                for (int u = 0; u < 7; u++) {
                    unsigned long long rp =
                        *(const unsigned long long*)(&s_sr[c][ir][x_base + u]);
                    #pragma unroll
                    for (int dx = 0; dx < 3; dx++) {
                        const int xx = u - dx;
                        if (xx >= 0 && xx < 5) {
                            #pragma unroll
                            for (int dy = 0; dy < 3; dy++) {
                                const int yy = ir - dy;
                                if (yy >= 0 && yy < 3)
                                    FMA_F32X2(acc[yy][xx], rp,
                                              wq[dy * 3 + dx], acc[yy][xx]);
                            }
                        }
                    }
                }
            }
        }

        int o_even = og * 2;
        #pragma unroll
        for (int yy = 0; yy < 3; yy++) {
            int y = y_base + yy;
            if (y >= OH_) continue;
            #pragma unroll
            for (int xx = 0; xx < 5; xx++) {
                float lo, hi;
                UNPACK2(lo, hi, acc[yy][xx]);
                int base = ct * (B_ * OC_ * OHW_) +
                           (b * OC_ + o_even) * OHW_ + y * OW_ + x_base + xx;
                g_part[base] = lo;
                if (o_even + 1 < OC_) g_part[base + OHW_] = hi;
            }
        }
    }
}

// sum partials + bias -> g_om
__global__ void reduce_om_kernel(const float* __restrict__ bias) {
    int t = blockIdx.x * 256 + threadIdx.x;
    if (t < B_ * OC_ * OHW_) {
        int oc = (t / OHW_) % OC_;
        float s = bias[oc];
        #pragma unroll
        for (int ct = 0; ct < CT_; ct++)
            s += g_part[ct * (B_ * OC_ * OHW_) + t];
        g_om[t] = s;
    }
}

// ---------------------------------------------------------------------------
// K3: deformable bilinear gather + weighted correlation (vectorized).
// grid = 1250 blocks, block = 256 = 4 groups x 64 threads (float4 channels).
// ---------------------------------------------------------------------------
__global__ void __launch_bounds__(256) deform_xcorr_kernel(float* __restrict__ out)
{
    __shared__ int4   sA4[4][K_];
    __shared__ float4 sW4[4][K_];

    const int tid = threadIdx.x;

    if (tid < 4 * K_) {
        const int g2 = tid / K_;
        const int k  = tid % K_;
        const int p  = blockIdx.x * 4 + g2;
        const int b  = p / OHW_;
        const int rem = p % OHW_;
        const int i  = rem / OW_;
        const int j  = rem % OW_;

        const int base = (b * OC_ + k) * OHW_ + i * OW_ + j;
        float oy = g_om[base];
        float ox = g_om[base + 49 * OHW_];
        float mz = g_om[base + 98 * OHW_];
        float m  = 1.0f / (1.0f + __expf(-mz));

        float ys = (float)i + (float)(k / T_) + oy;
        float xs = (float)j + (float)(k % T_) + ox;
        float y0f = floorf(ys), x0f = floorf(xs);
        float wy = ys - y0f, wx = xs - x0f;
        float y1f = y0f + 1.0f, x1f = x0f + 1.0f;

        bool vy0 = (y0f >= 0.0f) && (y0f <= (float)(H_ - 1));
        bool vy1 = (y1f >= 0.0f) && (y1f <= (float)(H_ - 1));
        bool vx0 = (x0f >= 0.0f) && (x0f <= (float)(W_ - 1));
        bool vx1 = (x1f >= 0.0f) && (x1f <= (float)(W_ - 1));

        float w00 = (1.0f - wy) * (1.0f - wx) * m; if (!(vy0 && vx0)) w00 = 0.0f;
        float w01 = (1.0f - wy) * wx          * m; if (!(vy0 && vx1)) w01 = 0.0f;
        float w10 = wy          * (1.0f - wx) * m; if (!(vy1 && vx0)) w10 = 0.0f;
        float w11 = wy          * wx          * m; if (!(vy1 && vx1)) w11 = 0.0f;

        int y0 = (int)fminf(fmaxf(y0f, 0.0f), (float)(H_ - 1));
        int y1 = (int)fminf(fmaxf(y1f, 0.0f), (float)(H_ - 1));
        int x0 = (int)fminf(fmaxf(x0f, 0.0f), (float)(W_ - 1));
        int x1 = (int)fminf(fmaxf(x1f, 0.0f), (float)(W_ - 1));

        sA4[g2][k] = make_int4((y0 * W_ + x0) * (C_ * 4),
                               (y0 * W_ + x1) * (C_ * 4),
                               (y1 * W_ + x0) * (C_ * 4),
                               (y1 * W_ + x1) * (C_ * 4));
        sW4[g2][k] = make_float4(w00, w01, w10, w11);
    }
    __syncthreads();

    const int g  = tid / 64;
    const int c4 = tid % 64;
    const int p  = blockIdx.x * 4 + g;
    const int b  = p / OHW_;
    const int rem = p % OHW_;
    const int i  = rem / OW_;
    const int j  = rem % OW_;

    const char* srTb = (const char*)(g_srT + (size_t)b * HW_ * C_) + c4 * 16;
    const float4* tT = (const float4*)(g_tmplT + (size_t)b * K_ * C_) + c4;

    float4 acc = make_float4(0.f, 0.f, 0.f, 0.f);
    #pragma unroll 7
    for (int k = 0; k < K_; k++) {
        int4   a  = sA4[g][k];
        float4 wv = sW4[g][k];
        float4 v00 = *(const float4*)(srTb + a.x);
        float4 v01 = *(const float4*)(srTb + a.y);
        float4 v10 = *(const float4*)(srTb + a.z);
        float4 v11 = *(const float4*)(srTb + a.w);
        float4 tv  = tT[(size_t)k * 64];

        float sx, sy, sz, sw;
        sx = wv.x * v00.x; sx = fmaf(wv.y, v01.x, sx); sx = fmaf(wv.z, v10.x, sx); sx = fmaf(wv.w, v11.x, sx);
        sy = wv.x * v00.y; sy = fmaf(wv.y, v01.y, sy); sy = fmaf(wv.z, v10.y, sy); sy = fmaf(wv.w, v11.y, sy);
        sz = wv.x * v00.z; sz = fmaf(wv.y, v01.z, sz); sz = fmaf(wv.z, v10.z, sz); sz = fmaf(wv.w, v11.z, sz);
        sw = wv.x * v00.w; sw = fmaf(wv.y, v01.w, sw); sw = fmaf(wv.z, v10.w, sw); sw = fmaf(wv.w, v11.w, sw);

        acc.x = fmaf(tv.x, sx, acc.x);
        acc.y = fmaf(tv.y, sy, acc.y);
        acc.z = fmaf(tv.z, sz, acc.z);
        acc.w = fmaf(tv.w, sw, acc.w);
    }

    const int c = c4 * 4;
    float* op = out + ((size_t)(b * C_ + c) * OH_ + i) * OW_ + j;
    op[0]        = acc.x;
    op[OHW_]     = acc.y;
    op[2 * OHW_] = acc.z;
    op[3 * OHW_] = acc.w;
}

// ---------------------------------------------------------------------------
extern "C" void kernel_launch(void* const* d_in, const int* in_sizes, int n_in,
                              void* d_out, int out_size)
{
    const float* sr   = (const float*)d_in[0];
    const float* tmpl = (const float*)d_in[1];
    const float* w    = (const float*)d_in[2];
    const float* bias = (const float*)d_in[3];
    float* out = (float*)d_out;

    prep_kernel<<<PREP_BLKS, 256>>>(sr, tmpl, w);
    {
        dim3 g(YT_, B_, CT_);
        conv_om_kernel<<<g, 384>>>(sr);
    }
    {
        int n = B_ * OC_ * OHW_;
        reduce_om_kernel<<<(n + 255) / 256, 256>>>(bias);
    }
    {
        deform_xcorr_kernel<<<1250, 256>>>(out);
    }
}

// round 9
// speedup vs baseline: 1.2561x; 1.2561x over previous
#include <cuda_runtime.h>
#include <cuda_fp16.h>
#include <cstdint>
#include <math.h>

// Problem constants
constexpr int B_  = 8;
constexpr int C_  = 256;
constexpr int H_  = 31;
constexpr int W_  = 31;
constexpr int T_  = 7;
constexpr int K_  = 49;      // T*T
constexpr int OC_ = 147;     // 3*K
constexpr int NP_ = 74;      // oc pairs (padded 148)
constexpr int OH_ = 25;
constexpr int OW_ = 25;
constexpr int HW_ = H_ * W_; // 961
constexpr int OHW_= OH_ * OW_; // 625
constexpr int CT_ = 4;       // C split tiles
constexpr int CPT_= C_ / CT_;// 64 channels per tile
constexpr int YT_ = 9;       // y tiles of 3 rows

// Scratch (device globals; no allocations allowed)
__device__ __half g_srH[B_ * HW_ * C_];                // (B,H,W,C) fp16
__device__ float  g_tmplT[B_ * K_ * C_];               // (B,K,C)
__device__ float  g_om[B_ * OC_ * OHW_];               // reduced conv out
__device__ float  g_part[CT_ * B_ * OC_ * OHW_];       // conv partials
__device__ float2 g_wpk[C_ * NP_ * 9];                 // packed weights [c][pair][tap]

// packed f32x2 helpers
#define FMA_F32X2(d, a, b, c) \
    asm("fma.rn.f32x2 %0, %1, %2, %3;" : "=l"(d) : "l"(a), "l"(b), "l"(c))
#define PACK_DUP(d, v) \
    asm("mov.b64 %0, {%1, %1};" : "=l"(d) : "f"(v))
#define UNPACK2(lo, hi, p) \
    asm("mov.b64 {%0, %1}, %2;" : "=f"(lo), "=f"(hi) : "l"(p))

// ---------------------------------------------------------------------------
// Fused prep: transpose sr (->fp16), transpose tmpl, pack weights.
// ---------------------------------------------------------------------------
constexpr int PREP_SR_BLKS   = 31 * 8 * 8;                   // 1984
constexpr int PREP_TMPL_BLKS = (B_ * K_ * C_ + 255) / 256;   // 392
constexpr int PREP_PACK_BLKS = (C_ * NP_ * 9 + 255) / 256;   // 666
constexpr int PREP_BLKS = PREP_SR_BLKS + PREP_TMPL_BLKS + PREP_PACK_BLKS;

__global__ void __launch_bounds__(256) prep_kernel(
    const float* __restrict__ sr,
    const float* __restrict__ tmpl,
    const float* __restrict__ w)
{
    __shared__ float tile[32][33];
    const int bid = blockIdx.x;
    const int tid = threadIdx.x;

    if (bid < PREP_SR_BLKS) {
        // transpose sr (B,C,HW) -> (B,HW,C) fp16; virtual grid (31, 8, 8)
        int px = bid % 31;
        int cy = (bid / 31) % 8;
        int b  = bid / (31 * 8);
        int p0 = px * 32, c0 = cy * 32;
        int tx = tid % 32, ty = tid / 32;
        #pragma unroll
        for (int yy = 0; yy < 32; yy += 8) {
            int c = c0 + ty + yy, p = p0 + tx;
            if (p < HW_) tile[ty + yy][tx] = sr[(b * C_ + c) * HW_ + p];
        }
        __syncthreads();
        #pragma unroll
        for (int yy = 0; yy < 32; yy += 8) {
            int p = p0 + ty + yy, c = c0 + tx;
            if (p < HW_) g_srH[(b * HW_ + p) * C_ + c] = __float2half(tile[tx][ty + yy]);
        }
    } else if (bid < PREP_SR_BLKS + PREP_TMPL_BLKS) {
        int t = (bid - PREP_SR_BLKS) * 256 + tid;
        if (t < B_ * K_ * C_) {
            int c = t % C_;
            int k = (t / C_) % K_;
            int b = t / (C_ * K_);
            g_tmplT[t] = tmpl[(b * C_ + c) * K_ + k];
        }
    } else {
        int t = (bid - PREP_SR_BLKS - PREP_TMPL_BLKS) * 256 + tid;
        if (t < C_ * NP_ * 9) {
            int tap = t % 9;
            int p   = (t / 9) % NP_;
            int c   = t / (9 * NP_);
            int o0 = 2 * p, o1 = 2 * p + 1;
            float v0 = w[o0 * (C_ * 9) + c * 9 + tap];
            float v1 = (o1 < OC_) ? w[o1 * (C_ * 9) + c * 9 + tap] : 0.0f;
            g_wpk[t] = make_float2(v0, v1);
        }
    }
}

// ---------------------------------------------------------------------------
// K2: 3x3 conv (R7 form — best measured). grid=(9,8,4)=288 blocks, 1 wave.
// block=384; og=tid/5 (74 oc-pairs), xg=tid%5, 3 output rows.
// sr slice staged once (scalar float smem); weights per-thread LDG.
// ---------------------------------------------------------------------------
__global__ void __launch_bounds__(384, 2) conv_om_kernel(
    const float* __restrict__ sr)
{
    __shared__ float s_sr[CPT_][5][33];   // 42.2 KB

    const int by = blockIdx.x;
    const int b  = blockIdx.y;
    const int ct = blockIdx.z;
    const int tid = threadIdx.x;

    const int og = tid / 5;
    const int xg = tid % 5;
    const bool active = (og < NP_);
    const int x_base = xg * 5;
    const int y_base = by * 3;
    const int cbase  = ct * CPT_;

    for (int e = tid; e < CPT_ * 5 * 33; e += 384) {
        int cc  = e / 165;
        int rem = e % 165;
        int r   = rem / 33;
        int xp  = rem % 33;
        int gy  = y_base + r - 1;
        int gx  = xp - 1;
        float v = 0.f;
        if (gy >= 0 && gy < H_ && gx >= 0 && gx < W_)
            v = sr[((b * C_ + cbase + cc) * H_ + gy) * W_ + gx];
        s_sr[cc][r][xp] = v;
    }
    __syncthreads();

    unsigned long long acc[3][5];
    #pragma unroll
    for (int yy = 0; yy < 3; yy++)
        #pragma unroll
        for (int xx = 0; xx < 5; xx++) acc[yy][xx] = 0ull;

    if (active) {
        const unsigned long long* __restrict__ wp0 =
            (const unsigned long long*)g_wpk + (size_t)og * 9;
        #pragma unroll 2
        for (int c = 0; c < CPT_; c++) {
            unsigned long long wq[9];
            const unsigned long long* wp = wp0 + (size_t)(cbase + c) * (NP_ * 9);
            #pragma unroll
            for (int t = 0; t < 9; t++) wq[t] = __ldg(wp + t);

            #pragma unroll
            for (int ir = 0; ir < 5; ir++) {
                #pragma unroll
                for (int u = 0; u < 7; u++) {
                    unsigned long long rp;
                    {
                        float v = s_sr[c][ir][x_base + u];
                        PACK_DUP(rp, v);
                    }
                    #pragma unroll
                    for (int dx = 0; dx < 3; dx++) {
                        const int xx = u - dx;
                        if (xx >= 0 && xx < 5) {
                            #pragma unroll
                            for (int dy = 0; dy < 3; dy++) {
                                const int yy = ir - dy;
                                if (yy >= 0 && yy < 3)
                                    FMA_F32X2(acc[yy][xx], rp,
                                              wq[dy * 3 + dx], acc[yy][xx]);
                            }
                        }
                    }
                }
            }
        }

        int o_even = og * 2;
        #pragma unroll
        for (int yy = 0; yy < 3; yy++) {
            int y = y_base + yy;
            if (y >= OH_) continue;
            #pragma unroll
            for (int xx = 0; xx < 5; xx++) {
                float lo, hi;
                UNPACK2(lo, hi, acc[yy][xx]);
                int base = ct * (B_ * OC_ * OHW_) +
                           (b * OC_ + o_even) * OHW_ + y * OW_ + x_base + xx;
                g_part[base] = lo;
                if (o_even + 1 < OC_) g_part[base + OHW_] = hi;
            }
        }
    }
}

// sum partials + bias -> g_om
__global__ void reduce_om_kernel(const float* __restrict__ bias) {
    int t = blockIdx.x * 256 + threadIdx.x;
    if (t < B_ * OC_ * OHW_) {
        int oc = (t / OHW_) % OC_;
        float s = bias[oc];
        #pragma unroll
        for (int ct = 0; ct < CT_; ct++)
            s += g_part[ct * (B_ * OC_ * OHW_) + t];
        g_om[t] = s;
    }
}

// ---------------------------------------------------------------------------
// K3: deformable bilinear gather + weighted correlation.
// Corners gathered in fp16 (halves l1tex wavefronts); math/accum in fp32.
// grid = 1250, block = 256 = 4 groups x 64 threads (4 channels each).
// ---------------------------------------------------------------------------
__global__ void __launch_bounds__(256) deform_xcorr_kernel(float* __restrict__ out)
{
    __shared__ int4   sA4[4][K_];   // byte offsets of 4 corners (in fp16 array)
    __shared__ float4 sW4[4][K_];

    const int tid = threadIdx.x;

    if (tid < 4 * K_) {
        const int g2 = tid / K_;
        const int k  = tid % K_;
        const int p  = blockIdx.x * 4 + g2;
        const int b  = p / OHW_;
        const int rem = p % OHW_;
        const int i  = rem / OW_;
        const int j  = rem % OW_;

        const int base = (b * OC_ + k) * OHW_ + i * OW_ + j;
        float oy = g_om[base];
        float ox = g_om[base + 49 * OHW_];
        float mz = g_om[base + 98 * OHW_];
        float m  = 1.0f / (1.0f + __expf(-mz));

        float ys = (float)i + (float)(k / T_) + oy;
        float xs = (float)j + (float)(k % T_) + ox;
        float y0f = floorf(ys), x0f = floorf(xs);
        float wy = ys - y0f, wx = xs - x0f;
        float y1f = y0f + 1.0f, x1f = x0f + 1.0f;

        bool vy0 = (y0f >= 0.0f) && (y0f <= (float)(H_ - 1));
        bool vy1 = (y1f >= 0.0f) && (y1f <= (float)(H_ - 1));
        bool vx0 = (x0f >= 0.0f) && (x0f <= (float)(W_ - 1));
        bool vx1 = (x1f >= 0.0f) && (x1f <= (float)(W_ - 1));

        float w00 = (1.0f - wy) * (1.0f - wx) * m; if (!(vy0 && vx0)) w00 = 0.0f;
        float w01 = (1.0f - wy) * wx          * m; if (!(vy0 && vx1)) w01 = 0.0f;
        float w10 = wy          * (1.0f - wx) * m; if (!(vy1 && vx0)) w10 = 0.0f;
        float w11 = wy          * wx          * m; if (!(vy1 && vx1)) w11 = 0.0f;

        int y0 = (int)fminf(fmaxf(y0f, 0.0f), (float)(H_ - 1));
        int y1 = (int)fminf(fmaxf(y1f, 0.0f), (float)(H_ - 1));
        int x0 = (int)fminf(fmaxf(x0f, 0.0f), (float)(W_ - 1));
        int x1 = (int)fminf(fmaxf(x1f, 0.0f), (float)(W_ - 1));

        sA4[g2][k] = make_int4((y0 * W_ + x0) * (C_ * 2),
                               (y0 * W_ + x1) * (C_ * 2),
                               (y1 * W_ + x0) * (C_ * 2),
                               (y1 * W_ + x1) * (C_ * 2));
        sW4[g2][k] = make_float4(w00, w01, w10, w11);
    }
    __syncthreads();

    const int g  = tid / 64;
    const int c4 = tid % 64;
    const int p  = blockIdx.x * 4 + g;
    const int b  = p / OHW_;
    const int rem = p % OHW_;
    const int i  = rem / OW_;
    const int j  = rem % OW_;

    const char* srHb = (const char*)g_srH + ((size_t)b * HW_ * C_ + c4 * 4) * 2;
    const float4* tT = (const float4*)(g_tmplT + (size_t)b * K_ * C_) + c4;

    float4 acc = make_float4(0.f, 0.f, 0.f, 0.f);
    #pragma unroll 7
    for (int k = 0; k < K_; k++) {
        int4   a  = sA4[g][k];
        float4 wv = sW4[g][k];

        uint2 u00 = *(const uint2*)(srHb + a.x);
        uint2 u01 = *(const uint2*)(srHb + a.y);
        uint2 u10 = *(const uint2*)(srHb + a.z);
        uint2 u11 = *(const uint2*)(srHb + a.w);

        float2 a00 = __half22float2(*reinterpret_cast<const __half2*>(&u00.x));
        float2 b00 = __half22float2(*reinterpret_cast<const __half2*>(&u00.y));
        float2 a01 = __half22float2(*reinterpret_cast<const __half2*>(&u01.x));
        float2 b01 = __half22float2(*reinterpret_cast<const __half2*>(&u01.y));
        float2 a10 = __half22float2(*reinterpret_cast<const __half2*>(&u10.x));
        float2 b10 = __half22float2(*reinterpret_cast<const __half2*>(&u10.y));
        float2 a11 = __half22float2(*reinterpret_cast<const __half2*>(&u11.x));
        float2 b11 = __half22float2(*reinterpret_cast<const __half2*>(&u11.y));

        float4 tv = tT[(size_t)k * 64];

        float sx, sy, sz, sw;
        sx = wv.x * a00.x; sx = fmaf(wv.y, a01.x, sx); sx = fmaf(wv.z, a10.x, sx); sx = fmaf(wv.w, a11.x, sx);
        sy = wv.x * a00.y; sy = fmaf(wv.y, a01.y, sy); sy = fmaf(wv.z, a10.y, sy); sy = fmaf(wv.w, a11.y, sy);
        sz = wv.x * b00.x; sz = fmaf(wv.y, b01.x, sz); sz = fmaf(wv.z, b10.x, sz); sz = fmaf(wv.w, b11.x, sz);
        sw = wv.x * b00.y; sw = fmaf(wv.y, b01.y, sw); sw = fmaf(wv.z, b10.y, sw); sw = fmaf(wv.w, b11.y, sw);

        acc.x = fmaf(tv.x, sx, acc.x);
        acc.y = fmaf(tv.y, sy, acc.y);
        acc.z = fmaf(tv.z, sz, acc.z);
        acc.w = fmaf(tv.w, sw, acc.w);
    }

    const int c = c4 * 4;
    float* op = out + ((size_t)(b * C_ + c) * OH_ + i) * OW_ + j;
    op[0]        = acc.x;
    op[OHW_]     = acc.y;
    op[2 * OHW_] = acc.z;
    op[3 * OHW_] = acc.w;
}

// ---------------------------------------------------------------------------
extern "C" void kernel_launch(void* const* d_in, const int* in_sizes, int n_in,
                              void* d_out, int out_size)
{
    const float* sr   = (const float*)d_in[0];
    const float* tmpl = (const float*)d_in[1];
    const float* w    = (const float*)d_in[2];
    const float* bias = (const float*)d_in[3];
    float* out = (float*)d_out;

    prep_kernel<<<PREP_BLKS, 256>>>(sr, tmpl, w);
    {
        dim3 g(YT_, B_, CT_);
        conv_om_kernel<<<g, 384>>>(sr);
    }
    {
        int n = B_ * OC_ * OHW_;
        reduce_om_kernel<<<(n + 255) / 256, 256>>>(bias);
    }
    {
        deform_xcorr_kernel<<<1250, 256>>>(out);
    }
}

// round 10
// speedup vs baseline: 1.2729x; 1.0134x over previous
#include <cuda_runtime.h>
#include <cuda_fp16.h>
#include <cstdint>
#include <math.h>

// Problem constants
constexpr int B_  = 8;
constexpr int C_  = 256;
constexpr int H_  = 31;
constexpr int W_  = 31;
constexpr int T_  = 7;
constexpr int K_  = 49;      // T*T
constexpr int OC_ = 147;     // 3*K
constexpr int NP_ = 74;      // oc pairs (padded 148)
constexpr int OH_ = 25;
constexpr int OW_ = 25;
constexpr int HW_ = H_ * W_; // 961
constexpr int OHW_= OH_ * OW_; // 625
constexpr int CT_ = 4;       // C split tiles
constexpr int CPT_= C_ / CT_;// 64 channels per tile
constexpr int YT_ = 9;       // y tiles of 3 rows

// Scratch (device globals; no allocations allowed)
__device__ __half g_srH[B_ * HW_ * C_];                // (B,H,W,C) fp16
__device__ __half g_tmplH[B_ * K_ * C_];               // (B,K,C) fp16
__device__ float  g_om[B_ * OC_ * OHW_];               // reduced conv out
__device__ float  g_part[CT_ * B_ * OC_ * OHW_];       // conv partials
__device__ float2 g_wpk[C_ * NP_ * 9];                 // packed weights [c][pair][tap]

// packed f32x2 helpers
#define FMA_F32X2(d, a, b, c) \
    asm("fma.rn.f32x2 %0, %1, %2, %3;" : "=l"(d) : "l"(a), "l"(b), "l"(c))
#define PACK_DUP(d, v) \
    asm("mov.b64 %0, {%1, %1};" : "=l"(d) : "f"(v))
#define UNPACK2(lo, hi, p) \
    asm("mov.b64 {%0, %1}, %2;" : "=f"(lo), "=f"(hi) : "l"(p))

// ---------------------------------------------------------------------------
// Fused prep: transpose sr (->fp16), transpose tmpl (->fp16), pack weights.
// ---------------------------------------------------------------------------
constexpr int PREP_SR_BLKS   = 31 * 8 * 8;                   // 1984
constexpr int PREP_TMPL_BLKS = (B_ * K_ * C_ + 255) / 256;   // 392
constexpr int PREP_PACK_BLKS = (C_ * NP_ * 9 + 255) / 256;   // 666
constexpr int PREP_BLKS = PREP_SR_BLKS + PREP_TMPL_BLKS + PREP_PACK_BLKS;

__global__ void __launch_bounds__(256) prep_kernel(
    const float* __restrict__ sr,
    const float* __restrict__ tmpl,
    const float* __restrict__ w)
{
    __shared__ float tile[32][33];
    const int bid = blockIdx.x;
    const int tid = threadIdx.x;

    if (bid < PREP_SR_BLKS) {
        // transpose sr (B,C,HW) -> (B,HW,C) fp16; virtual grid (31, 8, 8)
        int px = bid % 31;
        int cy = (bid / 31) % 8;
        int b  = bid / (31 * 8);
        int p0 = px * 32, c0 = cy * 32;
        int tx = tid % 32, ty = tid / 32;
        #pragma unroll
        for (int yy = 0; yy < 32; yy += 8) {
            int c = c0 + ty + yy, p = p0 + tx;
            if (p < HW_) tile[ty + yy][tx] = sr[(b * C_ + c) * HW_ + p];
        }
        __syncthreads();
        #pragma unroll
        for (int yy = 0; yy < 32; yy += 8) {
            int p = p0 + ty + yy, c = c0 + tx;
            if (p < HW_) g_srH[(b * HW_ + p) * C_ + c] = __float2half(tile[tx][ty + yy]);
        }
    } else if (bid < PREP_SR_BLKS + PREP_TMPL_BLKS) {
        int t = (bid - PREP_SR_BLKS) * 256 + tid;
        if (t < B_ * K_ * C_) {
            int c = t % C_;
            int k = (t / C_) % K_;
            int b = t / (C_ * K_);
            g_tmplH[t] = __float2half(tmpl[(b * C_ + c) * K_ + k]);
        }
    } else {
        int t = (bid - PREP_SR_BLKS - PREP_TMPL_BLKS) * 256 + tid;
        if (t < C_ * NP_ * 9) {
            int tap = t % 9;
            int p   = (t / 9) % NP_;
            int c   = t / (9 * NP_);
            int o0 = 2 * p, o1 = 2 * p + 1;
            float v0 = w[o0 * (C_ * 9) + c * 9 + tap];
            float v1 = (o1 < OC_) ? w[o1 * (C_ * 9) + c * 9 + tap] : 0.0f;
            g_wpk[t] = make_float2(v0, v1);
        }
    }
}

// ---------------------------------------------------------------------------
// K2: 3x3 conv (validated R7 form). grid=(9,8,4)=288 blocks, 1 wave.
// block=384; og=tid/5 (74 oc-pairs), xg=tid%5, 3 output rows.
// ---------------------------------------------------------------------------
__global__ void __launch_bounds__(384, 2) conv_om_kernel(
    const float* __restrict__ sr)
{
    __shared__ float s_sr[CPT_][5][33];   // 42.2 KB

    const int by = blockIdx.x;
    const int b  = blockIdx.y;
    const int ct = blockIdx.z;
    const int tid = threadIdx.x;

    const int og = tid / 5;
    const int xg = tid % 5;
    const bool active = (og < NP_);
    const int x_base = xg * 5;
    const int y_base = by * 3;
    const int cbase  = ct * CPT_;

    for (int e = tid; e < CPT_ * 5 * 33; e += 384) {
        int cc  = e / 165;
        int rem = e % 165;
        int r   = rem / 33;
        int xp  = rem % 33;
        int gy  = y_base + r - 1;
        int gx  = xp - 1;
        float v = 0.f;
        if (gy >= 0 && gy < H_ && gx >= 0 && gx < W_)
            v = sr[((b * C_ + cbase + cc) * H_ + gy) * W_ + gx];
        s_sr[cc][r][xp] = v;
    }
    __syncthreads();

    unsigned long long acc[3][5];
    #pragma unroll
    for (int yy = 0; yy < 3; yy++)
        #pragma unroll
        for (int xx = 0; xx < 5; xx++) acc[yy][xx] = 0ull;

    if (active) {
        const unsigned long long* __restrict__ wp0 =
            (const unsigned long long*)g_wpk + (size_t)og * 9;
        #pragma unroll 2
        for (int c = 0; c < CPT_; c++) {
            unsigned long long wq[9];
            const unsigned long long* wp = wp0 + (size_t)(cbase + c) * (NP_ * 9);
            #pragma unroll
            for (int t = 0; t < 9; t++) wq[t] = __ldg(wp + t);

            #pragma unroll
            for (int ir = 0; ir < 5; ir++) {
                #pragma unroll
                for (int u = 0; u < 7; u++) {
                    unsigned long long rp;
                    {
                        float v = s_sr[c][ir][x_base + u];
                        PACK_DUP(rp, v);
                    }
                    #pragma unroll
                    for (int dx = 0; dx < 3; dx++) {
                        const int xx = u - dx;
                        if (xx >= 0 && xx < 5) {
                            #pragma unroll
                            for (int dy = 0; dy < 3; dy++) {
                                const int yy = ir - dy;
                                if (yy >= 0 && yy < 3)
                                    FMA_F32X2(acc[yy][xx], rp,
                                              wq[dy * 3 + dx], acc[yy][xx]);
                            }
                        }
                    }
                }
            }
        }

        int o_even = og * 2;
        #pragma unroll
        for (int yy = 0; yy < 3; yy++) {
            int y = y_base + yy;
            if (y >= OH_) continue;
            #pragma unroll
            for (int xx = 0; xx < 5; xx++) {
                float lo, hi;
                UNPACK2(lo, hi, acc[yy][xx]);
                int base = ct * (B_ * OC_ * OHW_) +
                           (b * OC_ + o_even) * OHW_ + y * OW_ + x_base + xx;
                g_part[base] = lo;
                if (o_even + 1 < OC_) g_part[base + OHW_] = hi;
            }
        }
    }
}

// sum partials + bias -> g_om
__global__ void reduce_om_kernel(const float* __restrict__ bias) {
    int t = blockIdx.x * 256 + threadIdx.x;
    if (t < B_ * OC_ * OHW_) {
        int oc = (t / OHW_) % OC_;
        float s = bias[oc];
        #pragma unroll
        for (int ct = 0; ct < CT_; ct++)
            s += g_part[ct * (B_ * OC_ * OHW_) + t];
        g_om[t] = s;
    }
}

// ---------------------------------------------------------------------------
// K3: deformable bilinear gather + weighted correlation.
// Corners AND tmpl gathered in fp16; all math/accum fp32.
// grid = 1250, block = 256 = 4 groups x 64 threads (4 channels each).
// ---------------------------------------------------------------------------
__global__ void __launch_bounds__(256) deform_xcorr_kernel(float* __restrict__ out)
{
    __shared__ int4   sA4[4][K_];   // byte offsets of 4 corners (fp16 array)
    __shared__ float4 sW4[4][K_];

    const int tid = threadIdx.x;

    if (tid < 4 * K_) {
        const int g2 = tid / K_;
        const int k  = tid % K_;
        const int p  = blockIdx.x * 4 + g2;
        const int b  = p / OHW_;
        const int rem = p % OHW_;
        const int i  = rem / OW_;
        const int j  = rem % OW_;

        const int base = (b * OC_ + k) * OHW_ + i * OW_ + j;
        float oy = g_om[base];
        float ox = g_om[base + 49 * OHW_];
        float mz = g_om[base + 98 * OHW_];
        float m  = 1.0f / (1.0f + __expf(-mz));

        float ys = (float)i + (float)(k / T_) + oy;
        float xs = (float)j + (float)(k % T_) + ox;
        float y0f = floorf(ys), x0f = floorf(xs);
        float wy = ys - y0f, wx = xs - x0f;
        float y1f = y0f + 1.0f, x1f = x0f + 1.0f;

        bool vy0 = (y0f >= 0.0f) && (y0f <= (float)(H_ - 1));
        bool vy1 = (y1f >= 0.0f) && (y1f <= (float)(H_ - 1));
        bool vx0 = (x0f >= 0.0f) && (x0f <= (float)(W_ - 1));
        bool vx1 = (x1f >= 0.0f) && (x1f <= (float)(W_ - 1));

        float w00 = (1.0f - wy) * (1.0f - wx) * m; if (!(vy0 && vx0)) w00 = 0.0f;
        float w01 = (1.0f - wy) * wx          * m; if (!(vy0 && vx1)) w01 = 0.0f;
        float w10 = wy          * (1.0f - wx) * m; if (!(vy1 && vx0)) w10 = 0.0f;
        float w11 = wy          * wx          * m; if (!(vy1 && vx1)) w11 = 0.0f;

        int y0 = (int)fminf(fmaxf(y0f, 0.0f), (float)(H_ - 1));
        int y1 = (int)fminf(fmaxf(y1f, 0.0f), (float)(H_ - 1));
        int x0 = (int)fminf(fmaxf(x0f, 0.0f), (float)(W_ - 1));
        int x1 = (int)fminf(fmaxf(x1f, 0.0f), (float)(W_ - 1));

        sA4[g2][k] = make_int4((y0 * W_ + x0) * (C_ * 2),
                               (y0 * W_ + x1) * (C_ * 2),
                               (y1 * W_ + x0) * (C_ * 2),
                               (y1 * W_ + x1) * (C_ * 2));
        sW4[g2][k] = make_float4(w00, w01, w10, w11);
    }
    __syncthreads();

    const int g  = tid / 64;
    const int c4 = tid % 64;
    const int p  = blockIdx.x * 4 + g;
    const int b  = p / OHW_;
    const int rem = p % OHW_;
    const int i  = rem / OW_;
    const int j  = rem % OW_;

    const char* srHb = (const char*)g_srH + ((size_t)b * HW_ * C_ + c4 * 4) * 2;
    const char* tHb  = (const char*)g_tmplH + ((size_t)b * K_ * C_ + c4 * 4) * 2;

    float4 acc = make_float4(0.f, 0.f, 0.f, 0.f);
    #pragma unroll 7
    for (int k = 0; k < K_; k++) {
        int4   a  = sA4[g][k];
        float4 wv = sW4[g][k];

        uint2 u00 = *(const uint2*)(srHb + a.x);
        uint2 u01 = *(const uint2*)(srHb + a.y);
        uint2 u10 = *(const uint2*)(srHb + a.z);
        uint2 u11 = *(const uint2*)(srHb + a.w);
        uint2 ut  = *(const uint2*)(tHb + k * (C_ * 2));

        float2 a00 = __half22float2(*reinterpret_cast<const __half2*>(&u00.x));
        float2 b00 = __half22float2(*reinterpret_cast<const __half2*>(&u00.y));
        float2 a01 = __half22float2(*reinterpret_cast<const __half2*>(&u01.x));
        float2 b01 = __half22float2(*reinterpret_cast<const __half2*>(&u01.y));
        float2 a10 = __half22float2(*reinterpret_cast<const __half2*>(&u10.x));
        float2 b10 = __half22float2(*reinterpret_cast<const __half2*>(&u10.y));
        float2 a11 = __half22float2(*reinterpret_cast<const __half2*>(&u11.x));
        float2 b11 = __half22float2(*reinterpret_cast<const __half2*>(&u11.y));
        float2 t0  = __half22float2(*reinterpret_cast<const __half2*>(&ut.x));
        float2 t1  = __half22float2(*reinterpret_cast<const __half2*>(&ut.y));

        float sx, sy, sz, sw;
        sx = wv.x * a00.x; sx = fmaf(wv.y, a01.x, sx); sx = fmaf(wv.z, a10.x, sx); sx = fmaf(wv.w, a11.x, sx);
        sy = wv.x * a00.y; sy = fmaf(wv.y, a01.y, sy); sy = fmaf(wv.z, a10.y, sy); sy = fmaf(wv.w, a11.y, sy);
        sz = wv.x * b00.x; sz = fmaf(wv.y, b01.x, sz); sz = fmaf(wv.z, b10.x, sz); sz = fmaf(wv.w, b11.x, sz);
        sw = wv.x * b00.y; sw = fmaf(wv.y, b01.y, sw); sw = fmaf(wv.z, b10.y, sw); sw = fmaf(wv.w, b11.y, sw);

        acc.x = fmaf(t0.x, sx, acc.x);
        acc.y = fmaf(t0.y, sy, acc.y);
        acc.z = fmaf(t1.x, sz, acc.z);
        acc.w = fmaf(t1.y, sw, acc.w);
    }

    const int c = c4 * 4;
    float* op = out + ((size_t)(b * C_ + c) * OH_ + i) * OW_ + j;
    op[0]        = acc.x;
    op[OHW_]     = acc.y;
    op[2 * OHW_] = acc.z;
    op[3 * OHW_] = acc.w;
}

// ---------------------------------------------------------------------------
extern "C" void kernel_launch(void* const* d_in, const int* in_sizes, int n_in,
                              void* d_out, int out_size)
{
    const float* sr   = (const float*)d_in[0];
    const float* tmpl = (const float*)d_in[1];
    const float* w    = (const float*)d_in[2];
    const float* bias = (const float*)d_in[3];
    float* out = (float*)d_out;

    prep_kernel<<<PREP_BLKS, 256>>>(sr, tmpl, w);
    {
        dim3 g(YT_, B_, CT_);
        conv_om_kernel<<<g, 384>>>(sr);
    }
    {
        int n = B_ * OC_ * OHW_;
        reduce_om_kernel<<<(n + 255) / 256, 256>>>(bias);
    }
    {
        deform_xcorr_kernel<<<1250, 256>>>(out);
    }
}

// round 11
// speedup vs baseline: 1.2866x; 1.0108x over previous
#include <cuda_runtime.h>
#include <cuda_fp16.h>
#include <cstdint>
#include <math.h>

// Problem constants
constexpr int B_  = 8;
constexpr int C_  = 256;
constexpr int H_  = 31;
constexpr int W_  = 31;
constexpr int T_  = 7;
constexpr int K_  = 49;      // T*T
constexpr int OC_ = 147;     // 3*K
constexpr int NP_ = 74;      // oc pairs (padded 148)
constexpr int OH_ = 25;
constexpr int OW_ = 25;
constexpr int HW_ = H_ * W_; // 961
constexpr int OHW_= OH_ * OW_; // 625
constexpr int CT_ = 4;       // C split tiles
constexpr int CPT_= C_ / CT_;// 64 channels per tile
constexpr int YT_ = 9;       // y tiles of 3 rows

// Scratch (device globals; no allocations allowed)
__device__ __half g_srH[B_ * HW_ * C_];                // (B,H,W,C) fp16
__device__ __half g_tmplH[B_ * K_ * C_];               // (B,K,C) fp16
__device__ float  g_om[B_ * OC_ * OHW_];               // reduced conv out
__device__ float  g_part[CT_ * B_ * OC_ * OHW_];       // conv partials
__device__ float2 g_wpk[C_ * NP_ * 9];                 // packed weights [c][pair][tap]

// packed f32x2 helpers
#define FMA_F32X2(d, a, b, c) \
    asm("fma.rn.f32x2 %0, %1, %2, %3;" : "=l"(d) : "l"(a), "l"(b), "l"(c))
#define PACK_DUP(d, v) \
    asm("mov.b64 %0, {%1, %1};" : "=l"(d) : "f"(v))
#define UNPACK2(lo, hi, p) \
    asm("mov.b64 {%0, %1}, %2;" : "=f"(lo), "=f"(hi) : "l"(p))

__device__ __forceinline__ __half2 u2h(unsigned int u) {
    return *reinterpret_cast<const __half2*>(&u);
}

// ---------------------------------------------------------------------------
// Fused prep: transpose sr (->fp16), transpose tmpl (->fp16), pack weights.
// ---------------------------------------------------------------------------
constexpr int PREP_SR_BLKS   = 31 * 8 * 8;                   // 1984
constexpr int PREP_TMPL_BLKS = (B_ * K_ * C_ + 255) / 256;   // 392
constexpr int PREP_PACK_BLKS = (C_ * NP_ * 9 + 255) / 256;   // 666
constexpr int PREP_BLKS = PREP_SR_BLKS + PREP_TMPL_BLKS + PREP_PACK_BLKS;

__global__ void __launch_bounds__(256) prep_kernel(
    const float* __restrict__ sr,
    const float* __restrict__ tmpl,
    const float* __restrict__ w)
{
    __shared__ float tile[32][33];
    const int bid = blockIdx.x;
    const int tid = threadIdx.x;

    if (bid < PREP_SR_BLKS) {
        int px = bid % 31;
        int cy = (bid / 31) % 8;
        int b  = bid / (31 * 8);
        int p0 = px * 32, c0 = cy * 32;
        int tx = tid % 32, ty = tid / 32;
        #pragma unroll
        for (int yy = 0; yy < 32; yy += 8) {
            int c = c0 + ty + yy, p = p0 + tx;
            if (p < HW_) tile[ty + yy][tx] = sr[(b * C_ + c) * HW_ + p];
        }
        __syncthreads();
        #pragma unroll
        for (int yy = 0; yy < 32; yy += 8) {
            int p = p0 + ty + yy, c = c0 + tx;
            if (p < HW_) g_srH[(b * HW_ + p) * C_ + c] = __float2half(tile[tx][ty + yy]);
        }
    } else if (bid < PREP_SR_BLKS + PREP_TMPL_BLKS) {
        int t = (bid - PREP_SR_BLKS) * 256 + tid;
        if (t < B_ * K_ * C_) {
            int c = t % C_;
            int k = (t / C_) % K_;
            int b = t / (C_ * K_);
            g_tmplH[t] = __float2half(tmpl[(b * C_ + c) * K_ + k]);
        }
    } else {
        int t = (bid - PREP_SR_BLKS - PREP_TMPL_BLKS) * 256 + tid;
        if (t < C_ * NP_ * 9) {
            int tap = t % 9;
            int p   = (t / 9) % NP_;
            int c   = t / (9 * NP_);
            int o0 = 2 * p, o1 = 2 * p + 1;
            float v0 = w[o0 * (C_ * 9) + c * 9 + tap];
            float v1 = (o1 < OC_) ? w[o1 * (C_ * 9) + c * 9 + tap] : 0.0f;
            g_wpk[t] = make_float2(v0, v1);
        }
    }
}

// ---------------------------------------------------------------------------
// K2: 3x3 conv (validated form). grid=(9,8,4)=288 blocks, 1 wave.
// ---------------------------------------------------------------------------
__global__ void __launch_bounds__(384, 2) conv_om_kernel(
    const float* __restrict__ sr)
{
    __shared__ float s_sr[CPT_][5][33];   // 42.2 KB

    const int by = blockIdx.x;
    const int b  = blockIdx.y;
    const int ct = blockIdx.z;
    const int tid = threadIdx.x;

    const int og = tid / 5;
    const int xg = tid % 5;
    const bool active = (og < NP_);
    const int x_base = xg * 5;
    const int y_base = by * 3;
    const int cbase  = ct * CPT_;

    for (int e = tid; e < CPT_ * 5 * 33; e += 384) {
        int cc  = e / 165;
        int rem = e % 165;
        int r   = rem / 33;
        int xp  = rem % 33;
        int gy  = y_base + r - 1;
        int gx  = xp - 1;
        float v = 0.f;
        if (gy >= 0 && gy < H_ && gx >= 0 && gx < W_)
            v = sr[((b * C_ + cbase + cc) * H_ + gy) * W_ + gx];
        s_sr[cc][r][xp] = v;
    }
    __syncthreads();

    unsigned long long acc[3][5];
    #pragma unroll
    for (int yy = 0; yy < 3; yy++)
        #pragma unroll
        for (int xx = 0; xx < 5; xx++) acc[yy][xx] = 0ull;

    if (active) {
        const unsigned long long* __restrict__ wp0 =
            (const unsigned long long*)g_wpk + (size_t)og * 9;
        #pragma unroll 2
        for (int c = 0; c < CPT_; c++) {
            unsigned long long wq[9];
            const unsigned long long* wp = wp0 + (size_t)(cbase + c) * (NP_ * 9);
            #pragma unroll
            for (int t = 0; t < 9; t++) wq[t] = __ldg(wp + t);

            #pragma unroll
            for (int ir = 0; ir < 5; ir++) {
                #pragma unroll
                for (int u = 0; u < 7; u++) {
                    unsigned long long rp;
                    {
                        float v = s_sr[c][ir][x_base + u];
                        PACK_DUP(rp, v);
                    }
                    #pragma unroll
                    for (int dx = 0; dx < 3; dx++) {
                        const int xx = u - dx;
                        if (xx >= 0 && xx < 5) {
                            #pragma unroll
                            for (int dy = 0; dy < 3; dy++) {
                                const int yy = ir - dy;
                                if (yy >= 0 && yy < 3)
                                    FMA_F32X2(acc[yy][xx], rp,
                                              wq[dy * 3 + dx], acc[yy][xx]);
                            }
                        }
                    }
                }
            }
        }

        int o_even = og * 2;
        #pragma unroll
        for (int yy = 0; yy < 3; yy++) {
            int y = y_base + yy;
            if (y >= OH_) continue;
            #pragma unroll
            for (int xx = 0; xx < 5; xx++) {
                float lo, hi;
                UNPACK2(lo, hi, acc[yy][xx]);
                int base = ct * (B_ * OC_ * OHW_) +
                           (b * OC_ + o_even) * OHW_ + y * OW_ + x_base + xx;
                g_part[base] = lo;
                if (o_even + 1 < OC_) g_part[base + OHW_] = hi;
            }
        }
    }
}

// sum partials + bias -> g_om
__global__ void reduce_om_kernel(const float* __restrict__ bias) {
    int t = blockIdx.x * 256 + threadIdx.x;
    if (t < B_ * OC_ * OHW_) {
        int oc = (t / OHW_) % OC_;
        float s = bias[oc];
        #pragma unroll
        for (int ct = 0; ct < CT_; ct++)
            s += g_part[ct * (B_ * OC_ * OHW_) + t];
        g_om[t] = s;
    }
}

// ---------------------------------------------------------------------------
// K3: deformable bilinear gather + weighted correlation.
// Bilinear + modulation + template product in packed HALF2 (HFMA2/HMUL2);
// accumulation across the 49 taps in fp32.
// grid = 1250, block = 256 = 4 groups x 64 threads (4 channels each).
// ---------------------------------------------------------------------------
__global__ void __launch_bounds__(256) deform_xcorr_kernel(float* __restrict__ out)
{
    __shared__ int4  sA4[4][K_];   // byte offsets of 4 corners (fp16 array)
    __shared__ uint4 sWh[4][K_];   // duplicated half2 weights w00,w01,w10,w11

    const int tid = threadIdx.x;

    if (tid < 4 * K_) {
        const int g2 = tid / K_;
        const int k  = tid % K_;
        const int p  = blockIdx.x * 4 + g2;
        const int b  = p / OHW_;
        const int rem = p % OHW_;
        const int i  = rem / OW_;
        const int j  = rem % OW_;

        const int base = (b * OC_ + k) * OHW_ + i * OW_ + j;
        float oy = g_om[base];
        float ox = g_om[base + 49 * OHW_];
        float mz = g_om[base + 98 * OHW_];
        float m  = 1.0f / (1.0f + __expf(-mz));

        float ys = (float)i + (float)(k / T_) + oy;
        float xs = (float)j + (float)(k % T_) + ox;
        float y0f = floorf(ys), x0f = floorf(xs);
        float wy = ys - y0f, wx = xs - x0f;
        float y1f = y0f + 1.0f, x1f = x0f + 1.0f;

        bool vy0 = (y0f >= 0.0f) && (y0f <= (float)(H_ - 1));
        bool vy1 = (y1f >= 0.0f) && (y1f <= (float)(H_ - 1));
        bool vx0 = (x0f >= 0.0f) && (x0f <= (float)(W_ - 1));
        bool vx1 = (x1f >= 0.0f) && (x1f <= (float)(W_ - 1));

        float w00 = (1.0f - wy) * (1.0f - wx) * m; if (!(vy0 && vx0)) w00 = 0.0f;
        float w01 = (1.0f - wy) * wx          * m; if (!(vy0 && vx1)) w01 = 0.0f;
        float w10 = wy          * (1.0f - wx) * m; if (!(vy1 && vx0)) w10 = 0.0f;
        float w11 = wy          * wx          * m; if (!(vy1 && vx1)) w11 = 0.0f;

        int y0 = (int)fminf(fmaxf(y0f, 0.0f), (float)(H_ - 1));
        int y1 = (int)fminf(fmaxf(y1f, 0.0f), (float)(H_ - 1));
        int x0 = (int)fminf(fmaxf(x0f, 0.0f), (float)(W_ - 1));
        int x1 = (int)fminf(fmaxf(x1f, 0.0f), (float)(W_ - 1));

        sA4[g2][k] = make_int4((y0 * W_ + x0) * (C_ * 2),
                               (y0 * W_ + x1) * (C_ * 2),
                               (y1 * W_ + x0) * (C_ * 2),
                               (y1 * W_ + x1) * (C_ * 2));
        __half2 h00 = __float2half2_rn(w00);
        __half2 h01 = __float2half2_rn(w01);
        __half2 h10 = __float2half2_rn(w10);
        __half2 h11 = __float2half2_rn(w11);
        sWh[g2][k] = make_uint4(*reinterpret_cast<unsigned int*>(&h00),
                                *reinterpret_cast<unsigned int*>(&h01),
                                *reinterpret_cast<unsigned int*>(&h10),
                                *reinterpret_cast<unsigned int*>(&h11));
    }
    __syncthreads();

    const int g  = tid / 64;
    const int c4 = tid % 64;
    const int p  = blockIdx.x * 4 + g;
    const int b  = p / OHW_;
    const int rem = p % OHW_;
    const int i  = rem / OW_;
    const int j  = rem % OW_;

    const char* srHb = (const char*)g_srH + ((size_t)b * HW_ * C_ + c4 * 4) * 2;
    const char* tHb  = (const char*)g_tmplH + ((size_t)b * K_ * C_ + c4 * 4) * 2;

    float4 acc = make_float4(0.f, 0.f, 0.f, 0.f);
    #pragma unroll 7
    for (int k = 0; k < K_; k++) {
        int4  a  = sA4[g][k];
        uint4 wh = sWh[g][k];
        __half2 w00 = u2h(wh.x), w01 = u2h(wh.y), w10 = u2h(wh.z), w11 = u2h(wh.w);

        uint2 u00 = *(const uint2*)(srHb + a.x);
        uint2 u01 = *(const uint2*)(srHb + a.y);
        uint2 u10 = *(const uint2*)(srHb + a.z);
        uint2 u11 = *(const uint2*)(srHb + a.w);
        uint2 ut  = *(const uint2*)(tHb + k * (C_ * 2));

        // bilinear + modulation in half2 (channels c0,c1)
        __half2 vA = __hmul2(w00, u2h(u00.x));
        vA = __hfma2(w01, u2h(u01.x), vA);
        vA = __hfma2(w10, u2h(u10.x), vA);
        vA = __hfma2(w11, u2h(u11.x), vA);
        // channels c2,c3
        __half2 vB = __hmul2(w00, u2h(u00.y));
        vB = __hfma2(w01, u2h(u01.y), vB);
        vB = __hfma2(w10, u2h(u10.y), vB);
        vB = __hfma2(w11, u2h(u11.y), vB);

        __half2 pA = __hmul2(u2h(ut.x), vA);
        __half2 pB = __hmul2(u2h(ut.y), vB);

        float2 fA = __half22float2(pA);
        float2 fB = __half22float2(pB);
        acc.x += fA.x;
        acc.y += fA.y;
        acc.z += fB.x;
        acc.w += fB.y;
    }

    const int c = c4 * 4;
    float* op = out + ((size_t)(b * C_ + c) * OH_ + i) * OW_ + j;
    op[0]        = acc.x;
    op[OHW_]     = acc.y;
    op[2 * OHW_] = acc.z;
    op[3 * OHW_] = acc.w;
}

// ---------------------------------------------------------------------------
extern "C" void kernel_launch(void* const* d_in, const int* in_sizes, int n_in,
                              void* d_out, int out_size)
{
    const float* sr   = (const float*)d_in[0];
    const float* tmpl = (const float*)d_in[1];
    const float* w    = (const float*)d_in[2];
    const float* bias = (const float*)d_in[3];
    float* out = (float*)d_out;

    prep_kernel<<<PREP_BLKS, 256>>>(sr, tmpl, w);
    {
        dim3 g(YT_, B_, CT_);
        conv_om_kernel<<<g, 384>>>(sr);
    }
    {
        int n = B_ * OC_ * OHW_;
        reduce_om_kernel<<<(n + 255) / 256, 256>>>(bias);
    }
    {
        deform_xcorr_kernel<<<1250, 256>>>(out);
    }
}